// round 6
// baseline (speedup 1.0000x reference)
#include <cuda_runtime.h>
#include <cstdint>

// Problem constants (shapes fixed by the dataset; N/E re-derived from in_sizes).
#define NMAX   100032        // padded max nodes
#define CIN    128
#define CCAT   128           // mu(64) | logstd(64)
#define COUT   64
#define MAX_LOGSTD 10.0f

// Scratch (static __device__ globals — no allocation allowed).
__device__ __align__(128) float g_xs [ (size_t)NMAX * CIN  ];  // dinv[v] * x[v,:]
__device__ __align__(128) float g_acc[ (size_t)NMAX * CCAT ];  // edge accumulator, then GEMM out
__device__ __align__(128) float g_deg[ NMAX ];

// ---------------------------------------------------------------- K0: init
__global__ void k_init(int N) {
    int i = blockIdx.x * blockDim.x + threadIdx.x;
    int total4 = N * (CIN / 4);
    if (i < total4) ((float4*)g_acc)[i] = make_float4(0.f, 0.f, 0.f, 0.f);
    if (i < N) g_deg[i] = 1.0f;           // self-loop contributes 1 to every deg
}

// ---------------------------------------------------------------- K1: degrees
// edge_index is INT32 (JAX x64-disabled demotes the reference's int64).
__global__ void k_deg(const int* __restrict__ ei, int E) {
    int e = blockIdx.x * blockDim.x + threadIdx.x;
    if (e >= E) return;
    int d = ei[E + e];                    // dst row
    atomicAdd(&g_deg[d], 1.0f);           // RED (no return)
}

// ---------------------------------------------------------------- K2: xs = dinv * x
__global__ void k_scale(const float* __restrict__ x, int N) {
    int i = blockIdx.x * blockDim.x + threadIdx.x;   // one float4 each
    int v  = i >> 5;                                  // 32 float4 per row
    if (v >= N) return;
    int c4 = (i & 31) * 4;
    float dinv = rsqrtf(g_deg[v]);                    // deg >= 1 always
    float4 xv = *(const float4*)&x[(size_t)v * CIN + c4];
    float4 o  = make_float4(dinv * xv.x, dinv * xv.y, dinv * xv.z, dinv * xv.w);
    *(float4*)&g_xs[(size_t)v * CIN + c4] = o;
}

// ---------------------------------------------------------------- K3: edge scatter
// warp per edge, lane = 4-channel group; L2-resident gather + vector atomic.
// red.global requires a GLOBAL-window address -> explicit cvta.to.global.
__global__ void k_scatter(const int* __restrict__ ei, int E) {
    int i = blockIdx.x * blockDim.x + threadIdx.x;
    int e = i >> 5;
    if (e >= E) return;
    int lane = i & 31;
    int s = __ldg(&ei[e]);
    int d = __ldg(&ei[E + e]);
    float4 v = *(const float4*)&g_xs[(size_t)s * CIN + lane * 4];
    float* p = &g_acc[(size_t)d * CCAT + lane * 4];
    asm volatile("{\n\t"
                 ".reg .u64 pg;\n\t"
                 "cvta.to.global.u64 pg, %0;\n\t"
                 "red.global.add.v4.f32 [pg], {%1,%2,%3,%4};\n\t"
                 "}"
                 :: "l"(p), "f"(v.x), "f"(v.y), "f"(v.z), "f"(v.w) : "memory");
}

// ---------------------------------------------------------------- K4: fused GEMM
// agg[v,k] = dinv[v]*(acc[v,k] + xs[v,k]);  out[v,c] = sum_k agg[v,k]*Wcat[k,c]
// Wcat = [W_mu | W_ls]. Result overwritten in-place into g_acc (each block only
// reads/writes its own 64-row slab; all reads precede writes within the block).
#define BM 64
#define BK 32
#define BN 128
__global__ __launch_bounds__(256) void k_gemm(const float* __restrict__ Wmu,
                                              const float* __restrict__ Wls, int N) {
    __shared__ float As[BK][BM + 4];   // (BM+4)=68 keeps 16B alignment per row
    __shared__ float Bs[BK][BN];
    int tid  = threadIdx.x;
    int row0 = blockIdx.x * BM;
    int tr   = tid >> 5;               // 0..7  -> rows tr*8 .. tr*8+7
    int tc   = tid & 31;               // 0..31 -> cols tc*4 .. tc*4+3
    float acc[8][4];
    #pragma unroll
    for (int i = 0; i < 8; i++)
        #pragma unroll
        for (int j = 0; j < 4; j++) acc[i][j] = 0.f;

    #pragma unroll
    for (int kt = 0; kt < CIN; kt += BK) {
        // --- load A slab (64 rows x 32 k), computing agg on the fly
        #pragma unroll
        for (int it = 0; it < 2; it++) {
            int f   = tid + it * 256;          // 0..511 float4 slots
            int r   = f >> 3;                  // 0..63
            int kk4 = (f & 7) * 4;             // 0..28
            int grow = row0 + r;
            float4 va = make_float4(0.f, 0.f, 0.f, 0.f);
            if (grow < N) {
                float dinv = rsqrtf(g_deg[grow]);
                float4 a = *(const float4*)&g_acc[(size_t)grow * CCAT + kt + kk4];
                float4 x = *(const float4*)&g_xs [(size_t)grow * CIN  + kt + kk4];
                va = make_float4(dinv * (a.x + x.x), dinv * (a.y + x.y),
                                 dinv * (a.z + x.z), dinv * (a.w + x.w));
            }
            As[kk4 + 0][r] = va.x; As[kk4 + 1][r] = va.y;
            As[kk4 + 2][r] = va.z; As[kk4 + 3][r] = va.w;
        }
        // --- load B slab (32 k x 128 c) from Wmu|Wls
        #pragma unroll
        for (int it = 0; it < 4; it++) {
            int f  = tid + it * 256;           // 0..1023 float4 slots
            int kk = f >> 5;                   // 0..31
            int c4 = (f & 31) * 4;             // 0..124
            int gk = kt + kk;
            float4 w = (c4 < 64) ? *(const float4*)&Wmu[gk * 64 + c4]
                                 : *(const float4*)&Wls[gk * 64 + (c4 - 64)];
            *(float4*)&Bs[kk][c4] = w;
        }
        __syncthreads();
        // --- compute 8x4 microtile
        #pragma unroll
        for (int kk = 0; kk < BK; kk++) {
            float a8[8], b4[4];
            *(float4*)&a8[0] = *(const float4*)&As[kk][tr * 8];      // broadcast
            *(float4*)&a8[4] = *(const float4*)&As[kk][tr * 8 + 4];  // broadcast
            *(float4*)&b4[0] = *(const float4*)&Bs[kk][tc * 4];      // conflict-free
            #pragma unroll
            for (int i = 0; i < 8; i++)
                #pragma unroll
                for (int j = 0; j < 4; j++) acc[i][j] += a8[i] * b4[j];
        }
        __syncthreads();
    }
    // write back in-place
    #pragma unroll
    for (int i = 0; i < 8; i++) {
        int grow = row0 + tr * 8 + i;
        if (grow < N)
            *(float4*)&g_acc[(size_t)grow * CCAT + tc * 4] = *(float4*)&acc[i][0];
    }
}

// ---------------------------------------------------------------- K5: VGAE epilogue
__global__ void k_final(const float* __restrict__ bmu, const float* __restrict__ bls,
                        const float* __restrict__ eps, float* __restrict__ z, int N) {
    int i = blockIdx.x * blockDim.x + threadIdx.x;   // one float4 of output each
    int v  = i >> 4;                                  // 16 float4 per row (64 cols)
    if (v >= N) return;
    int c4 = (i & 15) * 4;
    float4 mu = *(const float4*)&g_acc[(size_t)v * CCAT + c4];
    float4 ls = *(const float4*)&g_acc[(size_t)v * CCAT + 64 + c4];
    float4 bm = *(const float4*)&bmu[c4];
    float4 bl = *(const float4*)&bls[c4];
    float4 ep = *(const float4*)&eps[(size_t)v * COUT + c4];
    float4 o;
    o.x = (mu.x + bm.x) + ep.x * expf(fminf(ls.x + bl.x, MAX_LOGSTD));
    o.y = (mu.y + bm.y) + ep.y * expf(fminf(ls.y + bl.y, MAX_LOGSTD));
    o.z = (mu.z + bm.z) + ep.z * expf(fminf(ls.z + bl.z, MAX_LOGSTD));
    o.w = (mu.w + bm.w) + ep.w * expf(fminf(ls.w + bl.w, MAX_LOGSTD));
    *(float4*)&z[(size_t)v * COUT + c4] = o;
}

// ---------------------------------------------------------------- launch
extern "C" void kernel_launch(void* const* d_in, const int* in_sizes, int n_in,
                              void* d_out, int out_size) {
    const float* x   = (const float*)d_in[0];
    const int*   ei  = (const int*)  d_in[1];   // int32! (JAX demotes int64)
    const float* Wmu = (const float*)d_in[2];
    const float* bmu = (const float*)d_in[3];
    const float* Wls = (const float*)d_in[4];
    const float* bls = (const float*)d_in[5];
    const float* eps = (const float*)d_in[6];
    float* z = (float*)d_out;

    int N = in_sizes[0] / CIN;      // 100000
    int E = in_sizes[1] / 2;        // 1600000

    int t = 256;
    k_init   <<<(N * (CIN/4) + t - 1) / t, t>>>(N);
    k_deg    <<<(E + t - 1) / t, t>>>(ei, E);
    k_scale  <<<(N * 32 + t - 1) / t, t>>>(x, N);
    k_scatter<<<((size_t)E * 32 + t - 1) / t, t>>>(ei, E);
    k_gemm   <<<(N + BM - 1) / BM, 256>>>(Wmu, Wls, N);
    k_final  <<<(N * 16 + t - 1) / t, t>>>(bmu, bls, eps, z, N);
    (void)n_in; (void)out_size;
}

// round 10
// speedup vs baseline: 1.3889x; 1.3889x over previous
#include <cuda_runtime.h>
#include <cstdint>

#define NMAX   100032
#define EMAX   1600000
#define CIN    128
#define CCAT   128
#define COUT   64
#define MAX_LOGSTD 10.0f
#define SCAN_T 256           // threads per scan block

// Scratch (__device__ globals — no allocation allowed).
__device__ __align__(128) float g_xs  [ (size_t)NMAX * CIN  ];  // dinv[v] * x[v,:]
__device__ __align__(128) float g_acc [ (size_t)NMAX * CCAT ];  // normalized aggregate
__device__ __align__(128) float g_dinv[ NMAX ];
__device__ int   g_cnt [ NMAX ];
__device__ int   g_off [ NMAX + 1 ];
__device__ int   g_cur [ NMAX ];
__device__ int   g_bsum[ 512 ];
__device__ int   g_boff[ 512 ];
__device__ int   g_csrc[ EMAX ];

// ---------------------------------------------------------------- zero counts
__global__ void k_zero(int N) {
    int i = blockIdx.x * blockDim.x + threadIdx.x;
    if (i < N) g_cnt[i] = 0;
}

// ---------------------------------------------------------------- count dst (edge_index is int32)
__global__ void k_count(const int* __restrict__ ei, int E) {
    int e = blockIdx.x * blockDim.x + threadIdx.x;
    if (e >= E) return;
    atomicAdd(&g_cnt[ei[E + e]], 1);
}

// ---------------------------------------------------------------- scan phase 1: per-block sums
__global__ void k_scan1(int N) {
    __shared__ int s[SCAN_T];
    int t = threadIdx.x, i = blockIdx.x * SCAN_T + t;
    s[t] = (i < N) ? g_cnt[i] : 0;
    __syncthreads();
    for (int d = SCAN_T / 2; d > 0; d >>= 1) {
        if (t < d) s[t] += s[t + d];
        __syncthreads();
    }
    if (t == 0) g_bsum[blockIdx.x] = s[0];
}

// ---------------------------------------------------------------- scan phase 2: scan block sums (1 block, 512 thr)
__global__ void k_scan2(int NB, int E, int N) {
    __shared__ int s[512];
    int t = threadIdx.x;
    int v = (t < NB) ? g_bsum[t] : 0;
    s[t] = v;
    __syncthreads();
    for (int d = 1; d < 512; d <<= 1) {
        int u = (t >= d) ? s[t - d] : 0;
        __syncthreads();
        s[t] += u;
        __syncthreads();
    }
    if (t < NB) g_boff[t] = s[t] - v;      // exclusive
    if (t == 0) g_off[N] = E;
}

// ---------------------------------------------------------------- scan phase 3: offsets, cursors, dinv
__global__ void k_scan3(int N) {
    __shared__ int s[SCAN_T];
    int t = threadIdx.x, i = blockIdx.x * SCAN_T + t;
    int c = (i < N) ? g_cnt[i] : 0;
    s[t] = c;
    __syncthreads();
    for (int d = 1; d < SCAN_T; d <<= 1) {
        int u = (t >= d) ? s[t - d] : 0;
        __syncthreads();
        s[t] += u;
        __syncthreads();
    }
    if (i < N) {
        int off = g_boff[blockIdx.x] + s[t] - c;   // exclusive
        g_off[i] = off;
        g_cur[i] = off;
        g_dinv[i] = rsqrtf((float)c + 1.0f);       // +1 self-loop
    }
}

// ---------------------------------------------------------------- fill CSR (src lists grouped by dst)
__global__ void k_fill(const int* __restrict__ ei, int E) {
    int e = blockIdx.x * blockDim.x + threadIdx.x;
    if (e >= E) return;
    int sIdx = ei[e];
    int d    = ei[E + e];
    int slot = atomicAdd(&g_cur[d], 1);
    g_csrc[slot] = sIdx;
}

// ---------------------------------------------------------------- xs = dinv * x
__global__ void k_scale(const float* __restrict__ x, int N) {
    int i = blockIdx.x * blockDim.x + threadIdx.x;
    int v  = i >> 5;
    if (v >= N) return;
    int c4 = (i & 31) * 4;
    float dinv = g_dinv[v];
    float4 xv = *(const float4*)&x[(size_t)v * CIN + c4];
    *(float4*)&g_xs[(size_t)v * CIN + c4] =
        make_float4(dinv * xv.x, dinv * xv.y, dinv * xv.z, dinv * xv.w);
}

// ---------------------------------------------------------------- gather: warp per node, no atomics
__global__ void k_gather(int N) {
    int gw   = (blockIdx.x * blockDim.x + threadIdx.x) >> 5;
    int lane = threadIdx.x & 31;
    if (gw >= N) return;
    int v = gw;
    int start = g_off[v], end = g_off[v + 1];
    const float4* xs4 = (const float4*)g_xs;
    float4 a = xs4[(size_t)v * 32 + lane];          // self-loop term
    int j = start;
    for (; j + 4 <= end; j += 4) {                  // MLP=4
        int s0 = g_csrc[j], s1 = g_csrc[j + 1], s2 = g_csrc[j + 2], s3 = g_csrc[j + 3];
        float4 a0 = xs4[(size_t)s0 * 32 + lane];
        float4 a1 = xs4[(size_t)s1 * 32 + lane];
        float4 a2 = xs4[(size_t)s2 * 32 + lane];
        float4 a3 = xs4[(size_t)s3 * 32 + lane];
        a.x += (a0.x + a1.x) + (a2.x + a3.x);
        a.y += (a0.y + a1.y) + (a2.y + a3.y);
        a.z += (a0.z + a1.z) + (a2.z + a3.z);
        a.w += (a0.w + a1.w) + (a2.w + a3.w);
    }
    for (; j < end; j++) {
        int s = g_csrc[j];
        float4 b = xs4[(size_t)s * 32 + lane];
        a.x += b.x; a.y += b.y; a.z += b.z; a.w += b.w;
    }
    float di = g_dinv[v];
    a.x *= di; a.y *= di; a.z *= di; a.w *= di;
    ((float4*)g_acc)[(size_t)v * 32 + lane] = a;
}

// ---------------------------------------------------------------- fused GEMM + VGAE epilogue
// out[v,c] = sum_k g_acc[v,k] * Wcat[k,c];  z = (mu+bmu) + eps*exp(min(ls+bls,10))
#define BM 64
#define BK 32
#define BN 128
__global__ __launch_bounds__(256) void k_gemm_fin(
        const float* __restrict__ Wmu, const float* __restrict__ Wls,
        const float* __restrict__ bmu, const float* __restrict__ bls,
        const float* __restrict__ eps, float* __restrict__ z, int N) {
    __shared__ float As[BK][BM + 4];
    __shared__ float Bs[BK][BN];
    __shared__ float Out[BM][BN + 4];
    __shared__ float bias[CCAT];
    int tid  = threadIdx.x;
    int row0 = blockIdx.x * BM;
    int tr   = tid >> 5;
    int tc   = tid & 31;
    if (tid < 64)       bias[tid]      = bmu[tid];
    else if (tid < 128) bias[tid]      = bls[tid - 64];
    float acc[8][4];
    #pragma unroll
    for (int i = 0; i < 8; i++)
        #pragma unroll
        for (int j = 0; j < 4; j++) acc[i][j] = 0.f;

    #pragma unroll
    for (int kt = 0; kt < CIN; kt += BK) {
        #pragma unroll
        for (int it = 0; it < 2; it++) {
            int f = tid + it * 256;
            int r = f >> 3;
            int kk4 = (f & 7) * 4;
            int grow = row0 + r;
            float4 va = make_float4(0.f, 0.f, 0.f, 0.f);
            if (grow < N)
                va = *(const float4*)&g_acc[(size_t)grow * CCAT + kt + kk4];
            As[kk4 + 0][r] = va.x; As[kk4 + 1][r] = va.y;
            As[kk4 + 2][r] = va.z; As[kk4 + 3][r] = va.w;
        }
        #pragma unroll
        for (int it = 0; it < 4; it++) {
            int f  = tid + it * 256;
            int kk = f >> 5;
            int c4 = (f & 31) * 4;
            int gk = kt + kk;
            float4 w = (c4 < 64) ? *(const float4*)&Wmu[gk * 64 + c4]
                                 : *(const float4*)&Wls[gk * 64 + (c4 - 64)];
            *(float4*)&Bs[kk][c4] = w;
        }
        __syncthreads();
        #pragma unroll
        for (int kk = 0; kk < BK; kk++) {
            float a8[8], b4[4];
            *(float4*)&a8[0] = *(const float4*)&As[kk][tr * 8];
            *(float4*)&a8[4] = *(const float4*)&As[kk][tr * 8 + 4];
            *(float4*)&b4[0] = *(const float4*)&Bs[kk][tc * 4];
            #pragma unroll
            for (int i = 0; i < 8; i++)
                #pragma unroll
                for (int j = 0; j < 4; j++) acc[i][j] += a8[i] * b4[j];
        }
        __syncthreads();
    }
    // stage result to smem, then epilogue
    #pragma unroll
    for (int i = 0; i < 8; i++)
        *(float4*)&Out[tr * 8 + i][tc * 4] = *(float4*)&acc[i][0];
    __syncthreads();
    #pragma unroll
    for (int it = 0; it < 16; it++) {
        int idx = tid + it * 256;          // 0..4095 over 64 rows x 64 cols
        int r = idx >> 6;
        int c = idx & 63;
        int v = row0 + r;
        if (v < N) {
            float mu = Out[r][c]      + bias[c];
            float ls = Out[r][c + 64] + bias[c + 64];
            z[(size_t)v * COUT + c] =
                mu + eps[(size_t)v * COUT + c] * expf(fminf(ls, MAX_LOGSTD));
        }
    }
}

// ---------------------------------------------------------------- launch
extern "C" void kernel_launch(void* const* d_in, const int* in_sizes, int n_in,
                              void* d_out, int out_size) {
    const float* x   = (const float*)d_in[0];
    const int*   ei  = (const int*)  d_in[1];   // int32 (JAX demotes int64)
    const float* Wmu = (const float*)d_in[2];
    const float* bmu = (const float*)d_in[3];
    const float* Wls = (const float*)d_in[4];
    const float* bls = (const float*)d_in[5];
    const float* eps = (const float*)d_in[6];
    float* z = (float*)d_out;

    int N = in_sizes[0] / CIN;      // 100000
    int E = in_sizes[1] / 2;        // 1600000
    int NB = (N + SCAN_T - 1) / SCAN_T;   // 391 (<=512)

    int t = 256;
    k_zero  <<<(N + t - 1) / t, t>>>(N);
    k_count <<<(E + t - 1) / t, t>>>(ei, E);
    k_scan1 <<<NB, SCAN_T>>>(N);
    k_scan2 <<<1, 512>>>(NB, E, N);
    k_scan3 <<<NB, SCAN_T>>>(N);
    k_fill  <<<(E + t - 1) / t, t>>>(ei, E);
    k_scale <<<(N * 32 + t - 1) / t, t>>>(x, N);
    k_gather<<<((size_t)N * 32 + t - 1) / t, t>>>(N);
    k_gemm_fin<<<(N + BM - 1) / BM, 256>>>(Wmu, Wls, bmu, bls, eps, z, N);
    (void)n_in; (void)out_size;
}

// round 13
// speedup vs baseline: 2.0852x; 1.5013x over previous
#include <cuda_runtime.h>
#include <cuda_fp16.h>
#include <cstdint>

#define NMAX   100032
#define EMAX   1600000
#define CIN    128
#define COUT   64
#define MAX_LOGSTD 10.0f
#define SCAN_T 256

// Scratch (__device__ globals — no allocation allowed).
__device__ __align__(128) __half g_xsh [ (size_t)NMAX * CIN ];  // fp16 dinv[v]*x[v,:]
__device__ __align__(128) __half g_acch[ (size_t)NMAX * CIN ];  // fp16 normalized aggregate
__device__ __align__(128) float g_dinv[ NMAX ];
__device__ int   g_cnt [ NMAX ];
__device__ int   g_off [ NMAX + 1 ];
__device__ int   g_cur [ NMAX ];
__device__ int   g_bsum[ 512 ];
__device__ int   g_boff[ 512 ];
__device__ int   g_csrc[ EMAX ];

// ---------------------------------------------------------------- zero counts
__global__ void k_zero(int N) {
    int i = blockIdx.x * blockDim.x + threadIdx.x;
    if (i < N) g_cnt[i] = 0;
}

// ---------------------------------------------------------------- count dst (edge_index is int32)
__global__ void k_count(const int* __restrict__ ei, int E) {
    int e = blockIdx.x * blockDim.x + threadIdx.x;
    if (e >= E) return;
    atomicAdd(&g_cnt[ei[E + e]], 1);
}

// ---------------------------------------------------------------- scan phase 1
__global__ void k_scan1(int N) {
    __shared__ int s[SCAN_T];
    int t = threadIdx.x, i = blockIdx.x * SCAN_T + t;
    s[t] = (i < N) ? g_cnt[i] : 0;
    __syncthreads();
    for (int d = SCAN_T / 2; d > 0; d >>= 1) {
        if (t < d) s[t] += s[t + d];
        __syncthreads();
    }
    if (t == 0) g_bsum[blockIdx.x] = s[0];
}

// ---------------------------------------------------------------- scan phase 2 (1 block)
__global__ void k_scan2(int NB, int E, int N) {
    __shared__ int s[512];
    int t = threadIdx.x;
    int v = (t < NB) ? g_bsum[t] : 0;
    s[t] = v;
    __syncthreads();
    for (int d = 1; d < 512; d <<= 1) {
        int u = (t >= d) ? s[t - d] : 0;
        __syncthreads();
        s[t] += u;
        __syncthreads();
    }
    if (t < NB) g_boff[t] = s[t] - v;      // exclusive
    if (t == 0) g_off[N] = E;
}

// ---------------------------------------------------------------- scan phase 3
__global__ void k_scan3(int N) {
    __shared__ int s[SCAN_T];
    int t = threadIdx.x, i = blockIdx.x * SCAN_T + t;
    int c = (i < N) ? g_cnt[i] : 0;
    s[t] = c;
    __syncthreads();
    for (int d = 1; d < SCAN_T; d <<= 1) {
        int u = (t >= d) ? s[t - d] : 0;
        __syncthreads();
        s[t] += u;
        __syncthreads();
    }
    if (i < N) {
        int off = g_boff[blockIdx.x] + s[t] - c;
        g_off[i] = off;
        g_cur[i] = off;
        g_dinv[i] = rsqrtf((float)c + 1.0f);       // +1 self-loop
    }
}

// ---------------------------------------------------------------- fill CSR
__global__ void k_fill(const int* __restrict__ ei, int E) {
    int e = blockIdx.x * blockDim.x + threadIdx.x;
    if (e >= E) return;
    int sIdx = ei[e];
    int d    = ei[E + e];
    int slot = atomicAdd(&g_cur[d], 1);
    g_csrc[slot] = sIdx;
}

// ---------------------------------------------------------------- xs = fp16(dinv * x)
__global__ void k_scale(const float* __restrict__ x, int N) {
    int i = blockIdx.x * blockDim.x + threadIdx.x;
    int v  = i >> 5;
    if (v >= N) return;
    int c4 = (i & 31) * 4;
    float dinv = g_dinv[v];
    float4 xv = *(const float4*)&x[(size_t)v * CIN + c4];
    __half2 h0 = __floats2half2_rn(dinv * xv.x, dinv * xv.y);
    __half2 h1 = __floats2half2_rn(dinv * xv.z, dinv * xv.w);
    uint2 u;
    u.x = *(uint32_t*)&h0; u.y = *(uint32_t*)&h1;
    *(uint2*)&g_xsh[(size_t)v * CIN + c4] = u;
}

// ---------------------------------------------------------------- gather (fp16 rows, fp32 accum)
__global__ void k_gather(int N) {
    int gw   = (blockIdx.x * blockDim.x + threadIdx.x) >> 5;
    int lane = threadIdx.x & 31;
    if (gw >= N) return;
    int v = gw;
    int start = g_off[v], end = g_off[v + 1];
    const __half* xs = g_xsh;
    float ax, ay, az, aw;
    {   // self-loop
        uint2 u = *(const uint2*)&xs[(size_t)v * CIN + lane * 4];
        float2 f0 = __half22float2(*(__half2*)&u.x);
        float2 f1 = __half22float2(*(__half2*)&u.y);
        ax = f0.x; ay = f0.y; az = f1.x; aw = f1.y;
    }
    int j = start;
    for (; j + 4 <= end; j += 4) {                  // MLP=4
        int s0 = g_csrc[j], s1 = g_csrc[j + 1], s2 = g_csrc[j + 2], s3 = g_csrc[j + 3];
        uint2 u0 = *(const uint2*)&xs[(size_t)s0 * CIN + lane * 4];
        uint2 u1 = *(const uint2*)&xs[(size_t)s1 * CIN + lane * 4];
        uint2 u2 = *(const uint2*)&xs[(size_t)s2 * CIN + lane * 4];
        uint2 u3 = *(const uint2*)&xs[(size_t)s3 * CIN + lane * 4];
        float2 a0 = __half22float2(*(__half2*)&u0.x), b0 = __half22float2(*(__half2*)&u0.y);
        float2 a1 = __half22float2(*(__half2*)&u1.x), b1 = __half22float2(*(__half2*)&u1.y);
        float2 a2 = __half22float2(*(__half2*)&u2.x), b2 = __half22float2(*(__half2*)&u2.y);
        float2 a3 = __half22float2(*(__half2*)&u3.x), b3 = __half22float2(*(__half2*)&u3.y);
        ax += (a0.x + a1.x) + (a2.x + a3.x);
        ay += (a0.y + a1.y) + (a2.y + a3.y);
        az += (b0.x + b1.x) + (b2.x + b3.x);
        aw += (b0.y + b1.y) + (b2.y + b3.y);
    }
    for (; j < end; j++) {
        int s = g_csrc[j];
        uint2 u = *(const uint2*)&xs[(size_t)s * CIN + lane * 4];
        float2 f0 = __half22float2(*(__half2*)&u.x);
        float2 f1 = __half22float2(*(__half2*)&u.y);
        ax += f0.x; ay += f0.y; az += f1.x; aw += f1.y;
    }
    float di = g_dinv[v];
    __half2 h0 = __floats2half2_rn(ax * di, ay * di);
    __half2 h1 = __floats2half2_rn(az * di, aw * di);
    uint2 o;
    o.x = *(uint32_t*)&h0; o.y = *(uint32_t*)&h1;
    *(uint2*)&g_acch[(size_t)v * CIN + lane * 4] = o;
}

// ---------------------------------------------------------------- tensor-core GEMM + VGAE epilogue
// C[64,128] = A[64,128](fp16, direct from gmem) x Wcat[128,128](fp16 smem), fp32 accum.
// All smem STATIC (< 48KB): B tile 34,816 B, reused as the fp32 Out tile after mainloop.
#define B_STR 136                 // halves per B smem row (8-half pad; 272B stride -> conflict-free trans-LDSM)
__global__ __launch_bounds__(256) void k_gemm_fin(
        const float* __restrict__ Wmu, const float* __restrict__ Wls,
        const float* __restrict__ bmu, const float* __restrict__ bls,
        const float* __restrict__ eps, float* __restrict__ z, int N) {
    __shared__ __align__(16) char buf[128 * B_STR * 2];   // 34,816 B: Bh, then Out
    __half* Bh  = (__half*)buf;                           // [128][B_STR] k-major
    float*  Out = (float*)buf;                            // [64][132] after mainloop
    __shared__ float bias[128];

    int tid  = threadIdx.x;
    int lane = tid & 31;
    int wid  = tid >> 5;
    int wm = wid >> 1;            // 0..3 -> rows wm*16
    int wn = wid & 1;             // 0..1 -> cols wn*64
    int row0 = blockIdx.x * 64;

    if (tid < 128) bias[tid] = (tid < 64) ? bmu[tid] : bls[tid - 64];

    // load+convert W tile (fp32 -> fp16, k-major rows of 128 cols = [Wmu|Wls])
    #pragma unroll
    for (int it = 0; it < 16; it++) {
        int f = tid + it * 256;           // 4096 float4 slots (128 k x 32)
        int k = f >> 5, c4 = (f & 31) * 4;
        float4 w = (c4 < 64) ? *(const float4*)&Wmu[k * 64 + c4]
                             : *(const float4*)&Wls[k * 64 + (c4 - 64)];
        __half2 h0 = __floats2half2_rn(w.x, w.y);
        __half2 h1 = __floats2half2_rn(w.z, w.w);
        uint2 u; u.x = *(uint32_t*)&h0; u.y = *(uint32_t*)&h1;
        *(uint2*)&Bh[k * B_STR + c4] = u;
    }
    __syncthreads();

    float c[8][4];
    #pragma unroll
    for (int t = 0; t < 8; t++)
        #pragma unroll
        for (int j = 0; j < 4; j++) c[t][j] = 0.f;

    // A fragment: direct global loads. Rows >= N read zeros (BSS-zeroed global,
    // gather never writes past N) -> contribute nothing; stores are guarded.
    int ar = row0 + wm * 16 + (lane >> 2);      // <= 100031 < NMAX, in-bounds
    int ac = (lane & 3) * 2;
    const __half* Ap = g_acch;

    uint32_t b_base = (uint32_t)__cvta_generic_to_shared(
        &Bh[(lane & 15) * B_STR + wn * 64]);

    #pragma unroll
    for (int ks = 0; ks < 8; ks++) {      // K = 8 x k16
        uint32_t a0 = *(const uint32_t*)&Ap[(size_t)ar       * CIN + ks * 16 + ac];
        uint32_t a1 = *(const uint32_t*)&Ap[(size_t)(ar + 8) * CIN + ks * 16 + ac];
        uint32_t a2 = *(const uint32_t*)&Ap[(size_t)ar       * CIN + ks * 16 + ac + 8];
        uint32_t a3 = *(const uint32_t*)&Ap[(size_t)(ar + 8) * CIN + ks * 16 + ac + 8];
        #pragma unroll
        for (int t = 0; t < 8; t++) {     // 8 n8 tiles (64 cols)
            uint32_t b0, b1;
            asm volatile("ldmatrix.sync.aligned.m8n8.x2.trans.shared.b16 {%0,%1}, [%2];"
                         : "=r"(b0), "=r"(b1)
                         : "r"(b_base + ks * (B_STR * 16 * 2) + t * 16));
            asm volatile("mma.sync.aligned.m16n8k16.row.col.f32.f16.f16.f32 "
                         "{%0,%1,%2,%3}, {%4,%5,%6,%7}, {%8,%9}, {%0,%1,%2,%3};"
                         : "+f"(c[t][0]), "+f"(c[t][1]), "+f"(c[t][2]), "+f"(c[t][3])
                         : "r"(a0), "r"(a1), "r"(a2), "r"(a3), "r"(b0), "r"(b1));
        }
    }
    __syncthreads();                      // done reading Bh; Out may overwrite

    // stage accum to smem Out[64][132]
    int g  = lane >> 2;
    int tq = lane & 3;
    #pragma unroll
    for (int t = 0; t < 8; t++) {
        int r   = wm * 16 + g;
        int col = wn * 64 + t * 8 + tq * 2;
        Out[r * 132 + col]           = c[t][0];
        Out[r * 132 + col + 1]       = c[t][1];
        Out[(r + 8) * 132 + col]     = c[t][2];
        Out[(r + 8) * 132 + col + 1] = c[t][3];
    }
    __syncthreads();

    // VGAE epilogue: z = (mu+bmu) + eps*exp(min(ls+bls, 10))
    #pragma unroll
    for (int it = 0; it < 16; it++) {
        int idx = tid + it * 256;         // 4096 = 64 rows x 64 cols
        int r = idx >> 6, cc = idx & 63;
        int v = row0 + r;
        if (v < N) {
            float mu = Out[r * 132 + cc]      + bias[cc];
            float ls = Out[r * 132 + cc + 64] + bias[cc + 64];
            z[(size_t)v * COUT + cc] =
                mu + eps[(size_t)v * COUT + cc] * expf(fminf(ls, MAX_LOGSTD));
        }
    }
}

// ---------------------------------------------------------------- launch
extern "C" void kernel_launch(void* const* d_in, const int* in_sizes, int n_in,
                              void* d_out, int out_size) {
    const float* x   = (const float*)d_in[0];
    const int*   ei  = (const int*)  d_in[1];   // int32 (JAX demotes int64)
    const float* Wmu = (const float*)d_in[2];
    const float* bmu = (const float*)d_in[3];
    const float* Wls = (const float*)d_in[4];
    const float* bls = (const float*)d_in[5];
    const float* eps = (const float*)d_in[6];
    float* z = (float*)d_out;

    int N = in_sizes[0] / CIN;      // 100000
    int E = in_sizes[1] / 2;        // 1600000
    int NB = (N + SCAN_T - 1) / SCAN_T;

    int t = 256;
    k_zero  <<<(N + t - 1) / t, t>>>(N);
    k_count <<<(E + t - 1) / t, t>>>(ei, E);
    k_scan1 <<<NB, SCAN_T>>>(N);
    k_scan2 <<<1, 512>>>(NB, E, N);
    k_scan3 <<<NB, SCAN_T>>>(N);
    k_fill  <<<(E + t - 1) / t, t>>>(ei, E);
    k_scale <<<(N * 32 + t - 1) / t, t>>>(x, N);
    k_gather<<<((size_t)N * 32 + t - 1) / t, t>>>(N);
    k_gemm_fin<<<(N + 63) / 64, 256>>>(Wmu, Wls, bmu, bls, eps, z, N);
    (void)n_in; (void)out_size;
}

// round 17
// speedup vs baseline: 2.2108x; 1.0602x over previous
#include <cuda_runtime.h>
#include <cuda_fp16.h>
#include <cstdint>

#define NMAX   100096        // >= 782*128 (GEMM M=128 tiles read unguarded)
#define EMAX   1600000
#define CIN    128
#define COUT   64
#define MAX_LOGSTD 10.0f
#define SCAN_T 256

// Scratch (__device__ globals — no allocation allowed).
__device__ __align__(128) __half g_xsh [ (size_t)NMAX * CIN ];  // fp16 dinv[v]*x[v,:]
__device__ __align__(128) __half g_acch[ (size_t)NMAX * CIN ];  // fp16 normalized aggregate
__device__ __align__(128) __half g_wh  [ CIN * 128 ];           // fp16 [Wmu|Wls], k-major
__device__ __align__(128) float g_dinv[ NMAX ];
__device__ int   g_cnt [ NMAX ];
__device__ int   g_off [ NMAX ];
__device__ int   g_cur [ NMAX ];
__device__ int   g_total;
__device__ int   g_csrc[ EMAX ];

// ---------------------------------------------------------------- K0: zero counts + cursor + W->fp16
__global__ void k_zero(const float* __restrict__ Wmu, const float* __restrict__ Wls, int N) {
    int i = blockIdx.x * blockDim.x + threadIdx.x;
    if (i < N) g_cnt[i] = 0;
    if (i == 0) g_total = 0;
    if (i < 4096) {                       // 4096 float4 slots = 128k x 32 cols
        int k = i >> 5, c4 = (i & 31) * 4;
        float4 w = (c4 < 64) ? *(const float4*)&Wmu[k * 64 + c4]
                             : *(const float4*)&Wls[k * 64 + (c4 - 64)];
        __half2 h0 = __floats2half2_rn(w.x, w.y);
        __half2 h1 = __floats2half2_rn(w.z, w.w);
        uint2 u; u.x = *(uint32_t*)&h0; u.y = *(uint32_t*)&h1;
        *(uint2*)&g_wh[k * 128 + c4] = u;
    }
}

// ---------------------------------------------------------------- K1: count dst (edge_index is int32)
__global__ void k_count(const int* __restrict__ ei, int E) {
    int e = blockIdx.x * blockDim.x + threadIdx.x;
    if (e >= E) return;
    atomicAdd(&g_cnt[ei[E + e]], 1);
}

// ---------------------------------------------------------------- K2: offsets via block scan + atomic base
__global__ void k_off(int N) {
    __shared__ int s[SCAN_T];
    __shared__ int base;
    int t = threadIdx.x, i = blockIdx.x * SCAN_T + t;
    int c = (i < N) ? g_cnt[i] : 0;
    s[t] = c;
    __syncthreads();
    for (int d = 1; d < SCAN_T; d <<= 1) {
        int u = (t >= d) ? s[t - d] : 0;
        __syncthreads();
        s[t] += u;
        __syncthreads();
    }
    if (t == SCAN_T - 1) base = atomicAdd(&g_total, s[t]);
    __syncthreads();
    if (i < N) {
        int off = base + s[t] - c;         // exclusive within block + global base
        g_off[i] = off;
        g_cur[i] = off;
        g_dinv[i] = rsqrtf((float)c + 1.0f);   // +1 self-loop
    }
}

// ---------------------------------------------------------------- K3: fill CSR
__global__ void k_fill(const int* __restrict__ ei, int E) {
    int e = blockIdx.x * blockDim.x + threadIdx.x;
    if (e >= E) return;
    int sIdx = ei[e];
    int d    = ei[E + e];
    int slot = atomicAdd(&g_cur[d], 1);
    g_csrc[slot] = sIdx;
}

// ---------------------------------------------------------------- K4: xs = fp16(dinv * x)
__global__ void k_scale(const float* __restrict__ x, int N) {
    int i = blockIdx.x * blockDim.x + threadIdx.x;
    int v  = i >> 5;
    if (v >= N) return;
    int c4 = (i & 31) * 4;
    float dinv = g_dinv[v];
    float4 xv = *(const float4*)&x[(size_t)v * CIN + c4];
    __half2 h0 = __floats2half2_rn(dinv * xv.x, dinv * xv.y);
    __half2 h1 = __floats2half2_rn(dinv * xv.z, dinv * xv.w);
    uint2 u;
    u.x = *(uint32_t*)&h0; u.y = *(uint32_t*)&h1;
    *(uint2*)&g_xsh[(size_t)v * CIN + c4] = u;
}

// ---------------------------------------------------------------- K5: gather (fp16 rows, fp32 accum, MLP=8)
__global__ void k_gather(int N) {
    int gw   = (blockIdx.x * blockDim.x + threadIdx.x) >> 5;
    int lane = threadIdx.x & 31;
    if (gw >= N) return;
    int v = gw;
    int start = g_off[v];
    int end   = start + g_cnt[v];
    const __half* xs = g_xsh;
    float ax, ay, az, aw;
    {   // self-loop
        uint2 u = *(const uint2*)&xs[(size_t)v * CIN + lane * 4];
        float2 f0 = __half22float2(*(__half2*)&u.x);
        float2 f1 = __half22float2(*(__half2*)&u.y);
        ax = f0.x; ay = f0.y; az = f1.x; aw = f1.y;
    }
    int j = start;
    for (; j + 8 <= end; j += 8) {                  // MLP=8
        int idx[8];
        #pragma unroll
        for (int q = 0; q < 8; q++) idx[q] = g_csrc[j + q];
        uint2 u[8];
        #pragma unroll
        for (int q = 0; q < 8; q++) u[q] = *(const uint2*)&xs[(size_t)idx[q] * CIN + lane * 4];
        #pragma unroll
        for (int q = 0; q < 8; q++) {
            float2 f0 = __half22float2(*(__half2*)&u[q].x);
            float2 f1 = __half22float2(*(__half2*)&u[q].y);
            ax += f0.x; ay += f0.y; az += f1.x; aw += f1.y;
        }
    }
    for (; j + 4 <= end; j += 4) {
        int s0 = g_csrc[j], s1 = g_csrc[j + 1], s2 = g_csrc[j + 2], s3 = g_csrc[j + 3];
        uint2 u0 = *(const uint2*)&xs[(size_t)s0 * CIN + lane * 4];
        uint2 u1 = *(const uint2*)&xs[(size_t)s1 * CIN + lane * 4];
        uint2 u2 = *(const uint2*)&xs[(size_t)s2 * CIN + lane * 4];
        uint2 u3 = *(const uint2*)&xs[(size_t)s3 * CIN + lane * 4];
        float2 a0 = __half22float2(*(__half2*)&u0.x), b0 = __half22float2(*(__half2*)&u0.y);
        float2 a1 = __half22float2(*(__half2*)&u1.x), b1 = __half22float2(*(__half2*)&u1.y);
        float2 a2 = __half22float2(*(__half2*)&u2.x), b2 = __half22float2(*(__half2*)&u2.y);
        float2 a3 = __half22float2(*(__half2*)&u3.x), b3 = __half22float2(*(__half2*)&u3.y);
        ax += (a0.x + a1.x) + (a2.x + a3.x);
        ay += (a0.y + a1.y) + (a2.y + a3.y);
        az += (b0.x + b1.x) + (b2.x + b3.x);
        aw += (b0.y + b1.y) + (b2.y + b3.y);
    }
    for (; j < end; j++) {
        int s = g_csrc[j];
        uint2 u = *(const uint2*)&xs[(size_t)s * CIN + lane * 4];
        float2 f0 = __half22float2(*(__half2*)&u.x);
        float2 f1 = __half22float2(*(__half2*)&u.y);
        ax += f0.x; ay += f0.y; az += f1.x; aw += f1.y;
    }
    float di = g_dinv[v];
    __half2 h0 = __floats2half2_rn(ax * di, ay * di);
    __half2 h1 = __floats2half2_rn(az * di, aw * di);
    uint2 o;
    o.x = *(uint32_t*)&h0; o.y = *(uint32_t*)&h1;
    *(uint2*)&g_acch[(size_t)v * CIN + lane * 4] = o;
}

// ---------------------------------------------------------------- K6: HMMA GEMM (M=128 tile) + VGAE epilogue
// C[128,128] = A[128,128](fp16, direct gmem) x Wcat[128,128](fp16 smem), fp32 accum.
// Epilogue: wn=1 warps stage ls through reused B buffer; wn=0 warps emit z.
#define B_STR 136                 // halves per B smem row (8-half pad -> conflict-free trans-LDSM)
#define LS_STR 68                 // floats per ls-exchange row (128*68*4 = 34816 = B buffer)
__global__ __launch_bounds__(512) void k_gemm_fin(
        const float* __restrict__ bmu, const float* __restrict__ bls,
        const float* __restrict__ eps, float* __restrict__ z, int N) {
    __shared__ __align__(16) char buf[128 * B_STR * 2];   // 34,816 B: Bh, then lsO
    __half* Bh  = (__half*)buf;                           // [128][B_STR] k-major
    float*  lsO = (float*)buf;                            // [128][LS_STR] after mainloop
    __shared__ float bias[128];

    int tid  = threadIdx.x;
    int lane = tid & 31;
    int wid  = tid >> 5;          // 0..15
    int wm = wid >> 1;            // 0..7 -> rows wm*16
    int wn = wid & 1;             // 0..1 -> cols wn*64
    int row0 = blockIdx.x * 128;

    if (tid < 128) bias[tid] = (tid < 64) ? bmu[tid] : bls[tid - 64];

    // load B tile from fp16 W (2048 uint4 slots: 128 k-rows x 16)
    #pragma unroll
    for (int it = 0; it < 4; it++) {
        int f = tid + it * 512;
        int k = f >> 4, c8 = (f & 15) * 8;
        uint4 u = *(const uint4*)&g_wh[k * 128 + c8];
        *(uint4*)&Bh[k * B_STR + c8] = u;
    }
    __syncthreads();

    float c[8][4];
    #pragma unroll
    for (int t = 0; t < 8; t++)
        #pragma unroll
        for (int j = 0; j < 4; j++) c[t][j] = 0.f;

    // A fragments straight from gmem (rows >= N are zero: BSS + guarded gather).
    int ar = row0 + wm * 16 + (lane >> 2);     // < NMAX by padding
    int ac = (lane & 3) * 2;
    const __half* Ap = g_acch;

    uint32_t b_base = (uint32_t)__cvta_generic_to_shared(
        &Bh[(lane & 15) * B_STR + wn * 64]);

    #pragma unroll
    for (int ks = 0; ks < 8; ks++) {      // K = 8 x k16
        uint32_t a0 = *(const uint32_t*)&Ap[(size_t)ar       * CIN + ks * 16 + ac];
        uint32_t a1 = *(const uint32_t*)&Ap[(size_t)(ar + 8) * CIN + ks * 16 + ac];
        uint32_t a2 = *(const uint32_t*)&Ap[(size_t)ar       * CIN + ks * 16 + ac + 8];
        uint32_t a3 = *(const uint32_t*)&Ap[(size_t)(ar + 8) * CIN + ks * 16 + ac + 8];
        #pragma unroll
        for (int t = 0; t < 8; t++) {     // 8 n8 tiles (64 cols per wn)
            uint32_t b0, b1;
            asm volatile("ldmatrix.sync.aligned.m8n8.x2.trans.shared.b16 {%0,%1}, [%2];"
                         : "=r"(b0), "=r"(b1)
                         : "r"(b_base + ks * (B_STR * 16 * 2) + t * 16));
            asm volatile("mma.sync.aligned.m16n8k16.row.col.f32.f16.f16.f32 "
                         "{%0,%1,%2,%3}, {%4,%5,%6,%7}, {%8,%9}, {%0,%1,%2,%3};"
                         : "+f"(c[t][0]), "+f"(c[t][1]), "+f"(c[t][2]), "+f"(c[t][3])
                         : "r"(a0), "r"(a1), "r"(a2), "r"(a3), "r"(b0), "r"(b1));
        }
    }
    __syncthreads();                      // everyone done reading Bh

    int g  = lane >> 2;
    int tq = lane & 3;
    if (wn == 1) {                        // stage logstd (cols 64..127) to smem
        #pragma unroll
        for (int t = 0; t < 8; t++) {
            int r   = wm * 16 + g;
            int col = t * 8 + tq * 2;     // ls-local col 0..63
            lsO[r * LS_STR + col]           = c[t][0];
            lsO[r * LS_STR + col + 1]       = c[t][1];
            lsO[(r + 8) * LS_STR + col]     = c[t][2];
            lsO[(r + 8) * LS_STR + col + 1] = c[t][3];
        }
    }
    __syncthreads();

    if (wn == 0) {                        // z = (mu+bmu) + eps*exp(min(ls+bls,10))
        #pragma unroll
        for (int t = 0; t < 8; t++) {
            int cc = t * 8 + tq * 2;
            #pragma unroll
            for (int half = 0; half < 2; half++) {
                int r = wm * 16 + g + half * 8;
                int v = row0 + r;
                if (v < N) {
                    float mu0 = c[t][half * 2 + 0] + bias[cc];
                    float mu1 = c[t][half * 2 + 1] + bias[cc + 1];
                    float ls0 = lsO[r * LS_STR + cc]     + bias[cc + 64];
                    float ls1 = lsO[r * LS_STR + cc + 1] + bias[cc + 65];
                    float2 ep = *(const float2*)&eps[(size_t)v * COUT + cc];
                    float2 o;
                    o.x = mu0 + ep.x * expf(fminf(ls0, MAX_LOGSTD));
                    o.y = mu1 + ep.y * expf(fminf(ls1, MAX_LOGSTD));
                    *(float2*)&z[(size_t)v * COUT + cc] = o;
                }
            }
        }
    }
}

// ---------------------------------------------------------------- launch
extern "C" void kernel_launch(void* const* d_in, const int* in_sizes, int n_in,
                              void* d_out, int out_size) {
    const float* x   = (const float*)d_in[0];
    const int*   ei  = (const int*)  d_in[1];   // int32 (JAX demotes int64)
    const float* Wmu = (const float*)d_in[2];
    const float* bmu = (const float*)d_in[3];
    const float* Wls = (const float*)d_in[4];
    const float* bls = (const float*)d_in[5];
    const float* eps = (const float*)d_in[6];
    float* z = (float*)d_out;

    int N = in_sizes[0] / CIN;      // 100000
    int E = in_sizes[1] / 2;        // 1600000
    int NB = (N + SCAN_T - 1) / SCAN_T;

    int t = 256;
    k_zero  <<<(N + t - 1) / t, t>>>(Wmu, Wls, N);
    k_count <<<(E + t - 1) / t, t>>>(ei, E);
    k_off   <<<NB, SCAN_T>>>(N);
    k_fill  <<<(E + t - 1) / t, t>>>(ei, E);
    k_scale <<<(N * 32 + t - 1) / t, t>>>(x, N);
    k_gather<<<((size_t)N * 32 + t - 1) / t, t>>>(N);
    k_gemm_fin<<<(N + 127) / 128, 512>>>(bmu, bls, eps, z, N);
    (void)n_in; (void)out_size;
}